// round 1
// baseline (speedup 1.0000x reference)
#include <cuda_runtime.h>

// End2End_7645041787474 — fused forward-pass collapse.
//
// Key identities (forward values only):
//   g = hard + y - stop_grad(y) == one_hot(argmax(logits + gumbel))   (y - y == 0)
//   argmax(softmax(z/1)) == argmax(z)
//   For l <  len[b]: embeds[b,l] = W[gidx]  (or 0 if gidx >= V),  nn_idx = gidx (or 0)
//   For l >= len[b]: embeds[b,l] = W[psg[b, l-len]],              nn_idx = psg[b, l-len]
//   (rwrt_attention is the prefix mask of len; the flip/roll/cumsum algebra
//    reduces exactly to the two cases above; psg[b,0]==1 guarantees flag=1
//    for all l >= len.)
//   cosine argmax of a single (or zero) embedding row against normalized W
//   is the row's own index (or 0 for the zero row).
//
// So: one kernel, one block per (b,l) row. Attention rows do a 2x32128-float
// argmax (the only real memory traffic); psg rows skip the logits read.

namespace {
constexpr int Bc  = 8;
constexpr int Lc  = 128;
constexpr int VFc = 32128;
constexpr int Vc  = 32100;
constexpr int Dc  = 768;
constexpr int NTHREADS = 256;
}

__global__ __launch_bounds__(NTHREADS)
void fused_gsm_embed_nn(const float* __restrict__ logits,
                        const float* __restrict__ gumbel,
                        const float* __restrict__ wemb,
                        const int*   __restrict__ rwrt,
                        const int*   __restrict__ psg,
                        float*       __restrict__ out)
{
    const int row = blockIdx.x;       // b*L + l
    const int b   = row >> 7;
    const int l   = row & 127;
    const int tid = threadIdx.x;

    __shared__ float s_val[NTHREADS];
    __shared__ int   s_idx[NTHREADS];
    __shared__ int   s_src;   // embedding row to gather, -1 => zero row
    __shared__ int   s_nn;

    const int att = rwrt[row];        // 1 iff l < len[b]

    if (att) {
        // ---- argmax over VF of (logits + gumbel) for this row ----
        const float4* lp = reinterpret_cast<const float4*>(logits + (size_t)row * VFc);
        const float4* gp = reinterpret_cast<const float4*>(gumbel + (size_t)row * VFc);
        float bestv = -3.402823466e38f;
        int   besti = 0;
        const int n4 = VFc / 4;       // 8032 float4s per row
        #pragma unroll 4
        for (int j = tid; j < n4; j += NTHREADS) {
            const float4 a = lp[j];
            const float4 c = gp[j];
            const float z0 = a.x + c.x;
            const float z1 = a.y + c.y;
            const float z2 = a.z + c.z;
            const float z3 = a.w + c.w;
            const int base = j << 2;
            // strict '>' keeps the first (lowest) index within this thread's
            // ascending scan — matches jnp.argmax tie-break.
            if (z0 > bestv) { bestv = z0; besti = base;     }
            if (z1 > bestv) { bestv = z1; besti = base + 1; }
            if (z2 > bestv) { bestv = z2; besti = base + 2; }
            if (z3 > bestv) { bestv = z3; besti = base + 3; }
        }
        s_val[tid] = bestv;
        s_idx[tid] = besti;
        __syncthreads();
        #pragma unroll
        for (int s = NTHREADS / 2; s > 0; s >>= 1) {
            if (tid < s) {
                const float v2 = s_val[tid + s];
                const int   i2 = s_idx[tid + s];
                if (v2 > s_val[tid] || (v2 == s_val[tid] && i2 < s_idx[tid])) {
                    s_val[tid] = v2;
                    s_idx[tid] = i2;
                }
            }
            __syncthreads();
        }
        if (tid == 0) {
            const int g = s_idx[0];
            s_src = (g < Vc) ? g : -1;  // gidx >= V => g[..., :V] is all-zero row
            s_nn  = (g < Vc) ? g : 0;   // zero row => sims all 0 => argmax = 0
        }
    } else {
        // ---- psg path: len[b] = sum of the 0/1 prefix mask ----
        s_idx[tid] = (tid < Lc) ? rwrt[b * Lc + tid] : 0;
        __syncthreads();
        #pragma unroll
        for (int s = NTHREADS / 2; s > 0; s >>= 1) {
            if (tid < s) s_idx[tid] += s_idx[tid + s];
            __syncthreads();
        }
        if (tid == 0) {
            const int len = s_idx[0];
            const int idx = psg[b * Lc + (l - len)];  // in [0, V)
            s_src = idx;
            s_nn  = idx;
        }
    }
    __syncthreads();

    // ---- write embeds row (gather one W row, or zeros) ----
    const int src = s_src;
    float4* orow = reinterpret_cast<float4*>(out + (size_t)row * Dc);
    if (tid < Dc / 4) {               // 192 float4s per row
        if (src >= 0) {
            const float4* wrow = reinterpret_cast<const float4*>(wemb + (size_t)src * Dc);
            orow[tid] = wrow[tid];
        } else {
            orow[tid] = make_float4(0.f, 0.f, 0.f, 0.f);
        }
    }

    // ---- write nn_idx (cast to float, appended after embeds) ----
    if (tid == 0) {
        out[(size_t)Bc * Lc * Dc + row] = (float)s_nn;
    }
}

extern "C" void kernel_launch(void* const* d_in, const int* in_sizes, int n_in,
                              void* d_out, int out_size) {
    const float* logits = (const float*)d_in[0];
    const float* gumbel = (const float*)d_in[1];
    const float* wemb   = (const float*)d_in[2];
    const int*   rwrt   = (const int*)d_in[3];
    const int*   psg    = (const int*)d_in[4];
    float*       out    = (float*)d_out;

    fused_gsm_embed_nn<<<Bc * Lc, NTHREADS>>>(logits, gumbel, wemb, rwrt, psg, out);
}